// round 4
// baseline (speedup 1.0000x reference)
#include <cuda_runtime.h>
#include <cuda_bf16.h>
#include <math.h>

#define BB   32
#define CC   2048
#define HWN  576
#define HW4  144       // HWN / 4
#define HWB2 288       // HWN / 2 (bf162 units per row)
#define PP   4
#define CHID 128
#define CP   8192
#define BCHUNK 8       // beta partial chunks (from fc2)
#define NHWC 9         // hw chunks of 64 in einsum

// ---- scratch (no allocations allowed) ----
__device__ __nv_bfloat162 g_xbf[BB * CC * HWB2];   // 75.5 MB bf16 copy of x
__device__ float g_pooled[BB * CC];
__device__ float g_hidden[BB * CHID];
__device__ float g_dw[BB * CP];                    // (B, P*C)
__device__ float g_beta_part[BCHUNK * BB * PP];

// ============================================================
// 1) pooled[b,c] = mean over HW; also write bf16 copy of x.
//    Warp per (b,c) row. fp32 reads are evict-first (streaming)
//    so they don't evict the L2-resident bf16 buffer.
// ============================================================
__global__ void k_pool(const float* __restrict__ x) {
    int warp = (blockIdx.x * blockDim.x + threadIdx.x) >> 5;   // row id
    int lane = threadIdx.x & 31;
    const float4* xr = reinterpret_cast<const float4*>(x) + (size_t)warp * HW4;
    uint2* xw = reinterpret_cast<uint2*>(g_xbf) + (size_t)warp * HW4;
    float s = 0.f;
    #pragma unroll
    for (int k = lane; k < HW4; k += 32) {
        float4 v = __ldcs(&xr[k]);                 // streaming read
        s += (v.x + v.y) + (v.z + v.w);
        __nv_bfloat162 lo = __float22bfloat162_rn(make_float2(v.x, v.y));
        __nv_bfloat162 hi = __float22bfloat162_rn(make_float2(v.z, v.w));
        uint2 u;
        u.x = *reinterpret_cast<unsigned int*>(&lo);
        u.y = *reinterpret_cast<unsigned int*>(&hi);
        xw[k] = u;                                  // normal (L2-resident) write
    }
    #pragma unroll
    for (int o = 16; o; o >>= 1) s += __shfl_xor_sync(0xffffffffu, s, o);
    if (lane == 0) g_pooled[warp] = s * (1.0f / 576.0f);
}

// ============================================================
// 2) hidden[b,j] = silu(dot(pooled[b,:], fc1_w[j,:]) + fc1_b[j])
// ============================================================
__global__ void k_fc1(const float* __restrict__ fc1_w,
                      const float* __restrict__ fc1_b) {
    int warp = (blockIdx.x * blockDim.x + threadIdx.x) >> 5;   // 0..4095
    int lane = threadIdx.x & 31;
    int b = warp >> 7;
    int j = warp & 127;
    const float4* pr = reinterpret_cast<const float4*>(g_pooled) + (size_t)b * (CC / 4);
    const float4* wr = reinterpret_cast<const float4*>(fc1_w)    + (size_t)j * (CC / 4);
    float s = 0.f;
    #pragma unroll 4
    for (int k = lane; k < CC / 4; k += 32) {
        float4 a = pr[k];
        float4 w = __ldg(&wr[k]);
        s += a.x * w.x + a.y * w.y + a.z * w.z + a.w * w.w;
    }
    #pragma unroll
    for (int o = 16; o; o >>= 1) s += __shfl_xor_sync(0xffffffffu, s, o);
    if (lane == 0) {
        float z = s + fc1_b[j];
        g_hidden[b * CHID + j] = z / (1.0f + expf(-z));
    }
}

// ============================================================
// 3) dw[b,row] = dot(hidden[b,:], fc2_w[row,:]) + fc2_b[row]
//    + fused beta partial reduction (conv_b . dw).
// ============================================================
__global__ void k_fc2(const float* __restrict__ fc2_w,
                      const float* __restrict__ fc2_b,
                      const float* __restrict__ conv_b) {
    __shared__ float4 hs[8 * 32];
    __shared__ float  red[8][256];
    int rc = blockIdx.x & 31;
    int bg = blockIdx.x >> 5;
    int t  = threadIdx.x;

    hs[t] = reinterpret_cast<const float4*>(g_hidden)[bg * 256 + t];
    __syncthreads();

    int row = rc * 256 + t;
    int p   = rc >> 3;
    int chi = rc & 7;
    int c   = chi * 256 + t;
    const float4* wr = reinterpret_cast<const float4*>(fc2_w) + (size_t)row * 32;
    float acc[8];
    #pragma unroll
    for (int bb = 0; bb < 8; bb++) acc[bb] = 0.f;

    #pragma unroll 4
    for (int j4 = 0; j4 < 32; j4++) {
        float4 w = __ldg(&wr[j4]);
        #pragma unroll
        for (int bb = 0; bb < 8; bb++) {
            float4 h = hs[bb * 32 + j4];
            acc[bb] += w.x * h.x + w.y * h.y + w.z * h.z + w.w * h.w;
        }
    }
    float bias = fc2_b[row];
    float cb   = __ldg(&conv_b[c]);
    #pragma unroll
    for (int bb = 0; bb < 8; bb++) {
        float d = acc[bb] + bias;
        g_dw[(size_t)(bg * 8 + bb) * CP + row] = d;
        red[bb][t] = cb * d;
    }
    __syncthreads();

    int wid  = t >> 5;
    int lane = t & 31;
    float s = red[wid][lane] + red[wid][lane + 32] + red[wid][lane + 64] +
              red[wid][lane + 96] + red[wid][lane + 128] + red[wid][lane + 160] +
              red[wid][lane + 192] + red[wid][lane + 224];
    #pragma unroll
    for (int o = 16; o; o >>= 1) s += __shfl_xor_sync(0xffffffffu, s, o);
    if (lane == 0)
        g_beta_part[((size_t)chi * BB + bg * 8 + wid) * PP + p] = s;
}

// ============================================================
// 4) Fused einsum + softmax. Block = (b, 64-hw chunk), ALL channels.
//    512 threads = 16 warps; warp w = channel stripe [w*128,(w+1)*128).
//    Thread lane owns 2 hw (one bf162), 8 fp32 accumulators.
//    Grid = 32*9 = 288 blocks, single wave (2/SM).
// ============================================================
__global__ void __launch_bounds__(512, 2) k_einsum(const float* __restrict__ conv_w,
                                                   float* __restrict__ out) {
    __shared__ float4 wcomb[CC];          // 32 KB: {p0..p3} per channel
    __shared__ float  red[16][64][PP];    // 16 KB: stripe partials
    __shared__ float  ssum[64][PP];
    __shared__ float  sbeta[PP];

    int blk = blockIdx.x;
    int b   = blk / NHWC;
    int hc  = blk % NHWC;                 // hw chunk (0..8)
    int t   = threadIdx.x;
    int w   = t >> 5;                     // stripe 0..15
    int lane = t & 31;

    // beta for this batch
    if (t < PP) {
        float bsum = 0.f;
        #pragma unroll
        for (int chi = 0; chi < BCHUNK; chi++)
            bsum += g_beta_part[((size_t)chi * BB + b) * PP + t];
        sbeta[t] = bsum;
    }
    // wcomb fill: 8192 floats
    const float* dwb = g_dw + (size_t)b * CP;
    for (int idx = t; idx < CC * PP; idx += 512) {
        int c = idx >> 2;
        int p = idx & 3;
        reinterpret_cast<float*>(wcomb)[idx] = __ldg(&conv_w[c]) * dwb[p * CC + c];
    }
    __syncthreads();

    // main accumulation
    const __nv_bfloat162* xb = g_xbf + ((size_t)b * CC + w * 128) * HWB2 + hc * 32 + lane;
    float a0x=0,a0y=0,a0z=0,a0w=0, a1x=0,a1y=0,a1z=0,a1w=0;
    #pragma unroll 8
    for (int ci = 0; ci < 128; ci++) {
        __nv_bfloat162 v = xb[(size_t)ci * HWB2];
        float2 f = __bfloat1622float2(v);
        float4 wc = wcomb[w * 128 + ci];
        a0x = fmaf(f.x, wc.x, a0x); a0y = fmaf(f.x, wc.y, a0y);
        a0z = fmaf(f.x, wc.z, a0z); a0w = fmaf(f.x, wc.w, a0w);
        a1x = fmaf(f.y, wc.x, a1x); a1y = fmaf(f.y, wc.y, a1y);
        a1z = fmaf(f.y, wc.z, a1z); a1w = fmaf(f.y, wc.w, a1w);
    }
    int hq = lane * 2;
    red[w][hq][0] = a0x; red[w][hq][1] = a0y; red[w][hq][2] = a0z; red[w][hq][3] = a0w;
    red[w][hq+1][0] = a1x; red[w][hq+1][1] = a1y; red[w][hq+1][2] = a1z; red[w][hq+1][3] = a1w;
    __syncthreads();

    // reduce 16 stripes: 256 threads, each one (hw, p)
    if (t < 256) {
        int hw = t >> 2;
        int p  = t & 3;
        float s = 0.f;
        #pragma unroll
        for (int st = 0; st < 16; st++) s += red[st][hw][p];
        ssum[hw][p] = s + sbeta[p];
    }
    __syncthreads();

    // softmax over P=4, 64 threads each own one hw
    if (t < 64) {
        float s0 = ssum[t][0], s1 = ssum[t][1], s2 = ssum[t][2], s3 = ssum[t][3];
        float m = fmaxf(fmaxf(s0, s1), fmaxf(s2, s3));
        float e0 = expf(s0 - m), e1 = expf(s1 - m), e2 = expf(s2 - m), e3 = expf(s3 - m);
        float inv = 1.f / (e0 + e1 + e2 + e3);
        size_t base = ((size_t)b * PP) * HWN + hc * 64 + t;
        out[base + 0 * HWN] = e0 * inv;
        out[base + 1 * HWN] = e1 * inv;
        out[base + 2 * HWN] = e2 * inv;
        out[base + 3 * HWN] = e3 * inv;
    }
}

extern "C" void kernel_launch(void* const* d_in, const int* in_sizes, int n_in,
                              void* d_out, int out_size) {
    const float* x      = (const float*)d_in[0];
    const float* fc1_w  = (const float*)d_in[1];
    const float* fc1_b  = (const float*)d_in[2];
    const float* fc2_w  = (const float*)d_in[3];
    const float* fc2_b  = (const float*)d_in[4];
    const float* conv_w = (const float*)d_in[5];
    const float* conv_b = (const float*)d_in[6];
    float* out = (float*)d_out;

    k_pool  <<<(BB * CC) / 8, 256>>>(x);                 // 8192 blocks
    k_fc1   <<<(BB * CHID) / 8, 256>>>(fc1_w, fc1_b);    // 512 blocks
    k_fc2   <<<128, 256>>>(fc2_w, fc2_b, conv_b);        // fused beta
    k_einsum<<<BB * NHWC, 512>>>(conv_w, out);           // 288 blocks, 1 wave
}

// round 5
// speedup vs baseline: 1.1908x; 1.1908x over previous
#include <cuda_runtime.h>
#include <cuda_fp16.h>
#include <math.h>

#define BB   32
#define CC   2048
#define HWN  576
#define HW4  144       // HWN / 4
#define PP   4
#define CHID 128
#define CP   8192
#define BCHUNK 8       // beta partial chunks (from fc2)
#define NHWC 9         // hw chunks of 64 in einsum

// ---- scratch (no allocations allowed) ----
__device__ unsigned int g_xq[BB * CC * HW4];       // 37.7 MB e4m3 copy of x (4 fp8 per u32)
__device__ float g_pooled[BB * CC];
__device__ float g_hidden[BB * CHID];
__device__ float g_dw[BB * CP];                    // (B, P*C)
__device__ float g_beta_part[BCHUNK * BB * PP];

// ============================================================
// 1) pooled[b,c] = mean over HW; also write e4m3 copy of x.
//    Warp per (b,c) row.
// ============================================================
__global__ void k_pool(const float* __restrict__ x) {
    int warp = (blockIdx.x * blockDim.x + threadIdx.x) >> 5;   // row id
    int lane = threadIdx.x & 31;
    const float4* xr = reinterpret_cast<const float4*>(x) + (size_t)warp * HW4;
    unsigned int* xw = g_xq + (size_t)warp * HW4;
    float s = 0.f;
    #pragma unroll
    for (int k = lane; k < HW4; k += 32) {
        float4 v = __ldcs(&xr[k]);
        s += (v.x + v.y) + (v.z + v.w);
        unsigned int u;
        asm("{\n\t"
            ".reg .b16 lo, hi;\n\t"
            "cvt.rn.satfinite.e4m3x2.f32 lo, %2, %1;\n\t"   // lo = {hi:v.y, lo:v.x}
            "cvt.rn.satfinite.e4m3x2.f32 hi, %4, %3;\n\t"   // hi = {hi:v.w, lo:v.z}
            "mov.b32 %0, {lo, hi};\n\t"
            "}" : "=r"(u) : "f"(v.x), "f"(v.y), "f"(v.z), "f"(v.w));
        xw[k] = u;
    }
    #pragma unroll
    for (int o = 16; o; o >>= 1) s += __shfl_xor_sync(0xffffffffu, s, o);
    if (lane == 0) g_pooled[warp] = s * (1.0f / 576.0f);
}

// ============================================================
// 2) hidden[b,j] = silu(dot(pooled[b,:], fc1_w[j,:]) + fc1_b[j])
// ============================================================
__global__ void k_fc1(const float* __restrict__ fc1_w,
                      const float* __restrict__ fc1_b) {
    int warp = (blockIdx.x * blockDim.x + threadIdx.x) >> 5;   // 0..4095
    int lane = threadIdx.x & 31;
    int b = warp >> 7;
    int j = warp & 127;
    const float4* pr = reinterpret_cast<const float4*>(g_pooled) + (size_t)b * (CC / 4);
    const float4* wr = reinterpret_cast<const float4*>(fc1_w)    + (size_t)j * (CC / 4);
    float s = 0.f;
    #pragma unroll 4
    for (int k = lane; k < CC / 4; k += 32) {
        float4 a = pr[k];
        float4 w = __ldg(&wr[k]);
        s += a.x * w.x + a.y * w.y + a.z * w.z + a.w * w.w;
    }
    #pragma unroll
    for (int o = 16; o; o >>= 1) s += __shfl_xor_sync(0xffffffffu, s, o);
    if (lane == 0) {
        float z = s + fc1_b[j];
        g_hidden[b * CHID + j] = z / (1.0f + expf(-z));
    }
}

// ============================================================
// 3) dw[b,row] = dot(hidden[b,:], fc2_w[row,:]) + fc2_b[row]
//    + fused beta partial reduction (conv_b . dw).
// ============================================================
__global__ void k_fc2(const float* __restrict__ fc2_w,
                      const float* __restrict__ fc2_b,
                      const float* __restrict__ conv_b) {
    __shared__ float4 hs[8 * 32];
    __shared__ float  red[8][256];
    int rc = blockIdx.x & 31;
    int bg = blockIdx.x >> 5;
    int t  = threadIdx.x;

    hs[t] = reinterpret_cast<const float4*>(g_hidden)[bg * 256 + t];
    __syncthreads();

    int row = rc * 256 + t;
    int p   = rc >> 3;
    int chi = rc & 7;
    int c   = chi * 256 + t;
    const float4* wr = reinterpret_cast<const float4*>(fc2_w) + (size_t)row * 32;
    float acc[8];
    #pragma unroll
    for (int bb = 0; bb < 8; bb++) acc[bb] = 0.f;

    #pragma unroll 4
    for (int j4 = 0; j4 < 32; j4++) {
        float4 w = __ldg(&wr[j4]);
        #pragma unroll
        for (int bb = 0; bb < 8; bb++) {
            float4 h = hs[bb * 32 + j4];
            acc[bb] += w.x * h.x + w.y * h.y + w.z * h.z + w.w * h.w;
        }
    }
    float bias = fc2_b[row];
    float cb   = __ldg(&conv_b[c]);
    #pragma unroll
    for (int bb = 0; bb < 8; bb++) {
        float d = acc[bb] + bias;
        g_dw[(size_t)(bg * 8 + bb) * CP + row] = d;
        red[bb][t] = cb * d;
    }
    __syncthreads();

    int wid  = t >> 5;
    int lane = t & 31;
    float s = red[wid][lane] + red[wid][lane + 32] + red[wid][lane + 64] +
              red[wid][lane + 96] + red[wid][lane + 128] + red[wid][lane + 160] +
              red[wid][lane + 192] + red[wid][lane + 224];
    #pragma unroll
    for (int o = 16; o; o >>= 1) s += __shfl_xor_sync(0xffffffffu, s, o);
    if (lane == 0)
        g_beta_part[((size_t)chi * BB + bg * 8 + wid) * PP + p] = s;
}

// ============================================================
// 4) Fused einsum + softmax. Block = (b, 64-hw chunk), ALL channels.
//    512 threads = 16 warps; warp w = channel stripe [w*128,(w+1)*128).
//    Lane owns 2 hw (one fp8x2 u16 load per channel), 8 fp32 accums.
//    Grid = 32*9 = 288 blocks, single wave (2/SM).
// ============================================================
__global__ void __launch_bounds__(512, 2) k_einsum(const float* __restrict__ conv_w,
                                                   float* __restrict__ out) {
    __shared__ float4 wcomb[CC];          // 32 KB: {p0..p3} per channel
    __shared__ float  red[16][64][PP];    // 16 KB
    __shared__ float  ssum[64][PP];
    __shared__ float  sbeta[PP];

    int blk = blockIdx.x;
    int b   = blk / NHWC;
    int hc  = blk % NHWC;                 // hw chunk (0..8)
    int t   = threadIdx.x;
    int w   = t >> 5;                     // stripe 0..15
    int lane = t & 31;

    if (t < PP) {
        float bsum = 0.f;
        #pragma unroll
        for (int chi = 0; chi < BCHUNK; chi++)
            bsum += g_beta_part[((size_t)chi * BB + b) * PP + t];
        sbeta[t] = bsum;
    }
    const float* dwb = g_dw + (size_t)b * CP;
    for (int idx = t; idx < CC * PP; idx += 512) {
        int c = idx >> 2;
        int p = idx & 3;
        reinterpret_cast<float*>(wcomb)[idx] = __ldg(&conv_w[c]) * dwb[p * CC + c];
    }
    __syncthreads();

    // main accumulation: u16 = 2 fp8 (2 consecutive hw)
    const unsigned short* xb = reinterpret_cast<const unsigned short*>(g_xq)
                             + ((size_t)b * CC + w * 128) * (HWN / 2) + hc * 32 + lane;
    float a0x=0,a0y=0,a0z=0,a0w=0, a1x=0,a1y=0,a1z=0,a1w=0;
    #pragma unroll 8
    for (int ci = 0; ci < 128; ci++) {
        unsigned short us = xb[(size_t)ci * (HWN / 2)];
        unsigned int h2;
        asm("cvt.rn.f16x2.e4m3x2 %0, %1;" : "=r"(h2) : "h"(us));
        float2 f = __half22float2(*reinterpret_cast<__half2*>(&h2));
        float4 wc = wcomb[w * 128 + ci];
        a0x = fmaf(f.x, wc.x, a0x); a0y = fmaf(f.x, wc.y, a0y);
        a0z = fmaf(f.x, wc.z, a0z); a0w = fmaf(f.x, wc.w, a0w);
        a1x = fmaf(f.y, wc.x, a1x); a1y = fmaf(f.y, wc.y, a1y);
        a1z = fmaf(f.y, wc.z, a1z); a1w = fmaf(f.y, wc.w, a1w);
    }
    int hq = lane * 2;
    red[w][hq][0] = a0x; red[w][hq][1] = a0y; red[w][hq][2] = a0z; red[w][hq][3] = a0w;
    red[w][hq+1][0] = a1x; red[w][hq+1][1] = a1y; red[w][hq+1][2] = a1z; red[w][hq+1][3] = a1w;
    __syncthreads();

    if (t < 256) {
        int hw = t >> 2;
        int p  = t & 3;
        float s = 0.f;
        #pragma unroll
        for (int st = 0; st < 16; st++) s += red[st][hw][p];
        ssum[hw][p] = s + sbeta[p];
    }
    __syncthreads();

    if (t < 64) {
        float s0 = ssum[t][0], s1 = ssum[t][1], s2 = ssum[t][2], s3 = ssum[t][3];
        float m = fmaxf(fmaxf(s0, s1), fmaxf(s2, s3));
        float e0 = expf(s0 - m), e1 = expf(s1 - m), e2 = expf(s2 - m), e3 = expf(s3 - m);
        float inv = 1.f / (e0 + e1 + e2 + e3);
        size_t base = ((size_t)b * PP) * HWN + hc * 64 + t;
        out[base + 0 * HWN] = e0 * inv;
        out[base + 1 * HWN] = e1 * inv;
        out[base + 2 * HWN] = e2 * inv;
        out[base + 3 * HWN] = e3 * inv;
    }
}

extern "C" void kernel_launch(void* const* d_in, const int* in_sizes, int n_in,
                              void* d_out, int out_size) {
    const float* x      = (const float*)d_in[0];
    const float* fc1_w  = (const float*)d_in[1];
    const float* fc1_b  = (const float*)d_in[2];
    const float* fc2_w  = (const float*)d_in[3];
    const float* fc2_b  = (const float*)d_in[4];
    const float* conv_w = (const float*)d_in[5];
    const float* conv_b = (const float*)d_in[6];
    float* out = (float*)d_out;

    k_pool  <<<(BB * CC) / 8, 256>>>(x);                 // 8192 blocks
    k_fc1   <<<(BB * CHID) / 8, 256>>>(fc1_w, fc1_b);    // 512 blocks
    k_fc2   <<<128, 256>>>(fc2_w, fc2_b, conv_b);        // fused beta
    k_einsum<<<BB * NHWC, 512>>>(conv_w, out);           // 288 blocks, 1 wave
}